// round 9
// baseline (speedup 1.0000x reference)
#include <cuda_runtime.h>
#include <cuda_bf16.h>
#include <float.h>
#include <stdint.h>

// Problem constants
#define BB 4
#define RR 128
#define CC 256
#define HH 64
#define WW 64
#define NREG 32
#define PS 3            // pool size (3x3)
#define IOU_THR 0.4f

// ---------------------------------------------------------------------------
// fix_axis: exact replica of the reference clip logic (ints, trunc==floor
// since operands are non-negative in the pad>0 branch).
// ---------------------------------------------------------------------------
__device__ __forceinline__ void fix_axis(int& mn, int& mx, int ps, int fs) {
    int pad = ps - (mx - mn);
    if (pad > 0) {
        bool fmin = mn < (pad / 2);
        bool fmx  = (fs - mx) < ((1 + pad) / 2);
        if (!fmin && !fmx) { mn = mn - pad / 2; mx = mx + (1 + pad) / 2; }
        if (fmin) { mn = 0; mx = ps; }
        if (fmx)  { mn = fs - ps; mx = fs; }   // fmx overrides fmin (ref order)
    }
}

// ---------------------------------------------------------------------------
// Fused kernel: every block (one per box*cell) redundantly computes its
// batch's NMS + clip in shared memory (~2us, concurrent across all blocks),
// then max-pools its 3x3 cell. 256 threads: 4 pixel-groups x 64 channel
// lanes (float4 per lane).
// ---------------------------------------------------------------------------
__global__ void __launch_bounds__(256)
roi_fused_kernel(const float* __restrict__ feat,
                 const float* __restrict__ roi,
                 float* __restrict__ out,
                 float* __restrict__ out_roic) {
    __shared__ float sx1[RR], sy1[RR], sx2[RR], sy2[RR], sar[RR];
    __shared__ uint32_t sup0[RR][4], sup1[RR][4];
    __shared__ int s_box[4];
    __shared__ float4 red[4][64];

    const int bid  = blockIdx.x;        // 0 .. B*N*9-1
    const int box  = bid / 9;           // 0 .. B*N-1
    const int cell = bid - box * 9;
    const int ci   = cell / 3;
    const int cj   = cell - ci * 3;
    const int b    = box >> 5;          // batch
    const int n    = box & (NREG - 1);  // region index within batch

    const int t = threadIdx.x;          // 0..255

    // ---- Phase 1a: load this batch's 128 boxes into smem -----------------
    if (t < RR) {
        const float* rp = roi + ((size_t)b * RR + t) * 4;
        float x = rp[0], y = rp[1], w = rp[2], h = rp[3];
        sx1[t] = x; sy1[t] = y; sx2[t] = x + w; sy2[t] = y + h; sar[t] = w * h;
    }
    __syncthreads();

    // ---- Phase 1b: suppression matrix. Row r split across 2 threads ------
    {
        const int r    = t & (RR - 1);
        const int half = t >> 7;        // 0 or 1
        float x = sx1[r], y = sy1[r], x2 = sx2[r], y2 = sy2[r], ar = sar[r];
        uint32_t row0 = 0, row1 = 0, row2 = 0, row3 = 0;
        for (int j = r + 1 + half; j < RR; j += 2) {
            float iw = fmaxf(fminf(x2, sx2[j]) - fmaxf(x, sx1[j]), 0.0f);
            float ih = fmaxf(fminf(y2, sy2[j]) - fmaxf(y, sy1[j]), 0.0f);
            float inter = iw * ih;
            float iou = __fdiv_rn(inter, ar + sar[j] - inter);  // IEEE rn
            if (iou > IOU_THR) {
                uint32_t bit = 1u << (j & 31);
                if      ((j >> 5) == 0) row0 |= bit;
                else if ((j >> 5) == 1) row1 |= bit;
                else if ((j >> 5) == 2) row2 |= bit;
                else                    row3 |= bit;
            }
        }
        uint32_t (*sp)[4] = half ? sup1 : sup0;
        sp[r][0] = row0; sp[r][1] = row1; sp[r][2] = row2; sp[r][3] = row3;
    }
    __syncthreads();

    // ---- Phase 1c: serial greedy walk + select + clip (thread 0) ---------
    if (t == 0) {
        uint32_t k0 = ~0u, k1 = ~0u, k2 = ~0u, k3 = ~0u;
        #pragma unroll 4
        for (int p = 0; p < RR - 1; ++p) {
            uint32_t s0 = sup0[p][0] | sup1[p][0];
            uint32_t s1 = sup0[p][1] | sup1[p][1];
            uint32_t s2 = sup0[p][2] | sup1[p][2];
            uint32_t s3 = sup0[p][3] | sup1[p][3];
            uint32_t kw = (p < 32) ? k0 : (p < 64) ? k1 : (p < 96) ? k2 : k3;
            uint32_t msk = 0u - ((kw >> (p & 31)) & 1u);
            k0 &= ~(s0 & msk); k1 &= ~(s1 & msk);
            k2 &= ~(s2 & msk); k3 &= ~(s3 & msk);
        }
        // n-th kept index (ascending), popcount rank walk; pad with R-1.
        // (R8 bug fixed: previous version could re-match cnt==n in later
        //  words and overwrite the selection.)
        uint32_t kwords[4] = {k0, k1, k2, k3};
        int p_sel = RR - 1;
        int rem = n;
        #pragma unroll
        for (int wrd = 0; wrd < 4; ++wrd) {
            uint32_t kw = kwords[wrd];
            int pc = __popc(kw);
            if (rem < pc) {
                uint32_t m = kw;
                for (int s = 0; s < rem; ++s) m &= m - 1;  // strip rem low bits
                p_sel = wrd * 32 + (__ffs(m) - 1);
                break;
            }
            rem -= pc;
        }
        // clip
        float bx = sx1[p_sel], by = sy1[p_sel], bx2 = sx2[p_sel], by2 = sy2[p_sel];
        int xmn = (int)fmaxf(0.0f, bx);
        int ymn = (int)fmaxf(0.0f, by);
        int xmx = (int)fminf((float)WW, bx2);
        int ymx = (int)fminf((float)HH, by2);
        fix_axis(xmn, xmx, PS, WW);
        fix_axis(ymn, ymx, PS, HH);
        s_box[0] = xmn; s_box[1] = ymn; s_box[2] = xmx - xmn; s_box[3] = ymx - ymn;

        if (cell == 0) {   // exactly one block per box writes the roic tail
            int o = box * 4;
            out_roic[o + 0] = (float)xmn;
            out_roic[o + 1] = (float)ymn;
            out_roic[o + 2] = (float)(xmx - xmn);
            out_roic[o + 3] = (float)(ymx - ymn);
        }
    }
    __syncthreads();

    // ---- Phase 2: max-pool this cell -------------------------------------
    const int x = s_box[0], y = s_box[1], w = s_box[2], h = s_box[3];
    const int d = h / PS;               // >= 1
    const int e = w / PS;
    const int r0 = y + ci * d;
    const int r1 = (ci < 2) ? (r0 + d) : (y + h);
    const int c0 = x + cj * e;
    const int c1 = (cj < 2) ? (c0 + e) : (x + w);

    const int g  = t >> 6;              // pixel group 0..3
    const int ch = t & 63;              // float4 channel lane

    const int ncol = c1 - c0;           // >= 1
    const int npix = (r1 - r0) * ncol;  // >= 1
    const float inv = 1.0f / (float)ncol;

    const float4* __restrict__ f4 =
        (const float4*)feat + ((size_t)b * HH * WW) * (CC / 4) + ch;

    float4 m = make_float4(-FLT_MAX, -FLT_MAX, -FLT_MAX, -FLT_MAX);

    // Independent iterations: (r,c) from linear index via guarded float
    // floor-div ((i+0.5)*inv; margin 0.5/ncol >= 0.0078 >> fp error ~1e-5).
    #pragma unroll 4
    for (int i = g; i < npix; i += 4) {
        int rr = (int)(((float)i + 0.5f) * inv);
        int cc = i - rr * ncol;
        float4 v = __ldg(f4 + (size_t)((r0 + rr) * WW + c0 + cc) * (CC / 4));
        m.x = fmaxf(m.x, v.x);
        m.y = fmaxf(m.y, v.y);
        m.z = fmaxf(m.z, v.z);
        m.w = fmaxf(m.w, v.w);
    }

    red[g][ch] = m;
    __syncthreads();

    if (t < 64) {
        float4 a0 = red[0][t], a1 = red[1][t], a2 = red[2][t], a3 = red[3][t];
        float4 o;
        o.x = fmaxf(fmaxf(a0.x, a1.x), fmaxf(a2.x, a3.x));
        o.y = fmaxf(fmaxf(a0.y, a1.y), fmaxf(a2.y, a3.y));
        o.z = fmaxf(fmaxf(a0.z, a1.z), fmaxf(a2.z, a3.z));
        o.w = fmaxf(fmaxf(a0.w, a1.w), fmaxf(a2.w, a3.w));
        // pooled layout (B, N, 3, 3, C): offset = bid * C + 4t
        ((float4*)out)[(size_t)bid * (CC / 4) + t] = o;
    }
}

// ---------------------------------------------------------------------------
// Launch: out = [pooled (B*N*3*3*C floats) | roi_clipped (B*N*4 as floats)]
// ---------------------------------------------------------------------------
extern "C" void kernel_launch(void* const* d_in, const int* in_sizes, int n_in,
                              void* d_out, int out_size) {
    const float* features = (const float*)d_in[0];  // (B,H,W,C) f32
    const float* roi      = (const float*)d_in[1];  // (B,R,4)  f32
    float* out = (float*)d_out;

    const int pooled_elems = BB * NREG * PS * PS * CC;  // 294912

    roi_fused_kernel<<<BB * NREG * 9, 256>>>(features, roi, out,
                                             out + pooled_elems);
}

// round 10
// speedup vs baseline: 1.6235x; 1.6235x over previous
#include <cuda_runtime.h>
#include <cuda_bf16.h>
#include <float.h>
#include <stdint.h>

// Problem constants
#define BB 4
#define RR 128
#define CC 256
#define HH 64
#define WW 64
#define NREG 32
#define PS 3            // pool size (3x3)
#define IOU_THR 0.4f

// ---------------------------------------------------------------------------
// fix_axis: exact replica of the reference clip logic (ints, trunc==floor
// since operands are non-negative in the pad>0 branch).
// ---------------------------------------------------------------------------
__device__ __forceinline__ void fix_axis(int& mn, int& mx, int ps, int fs) {
    int pad = ps - (mx - mn);
    if (pad > 0) {
        bool fmin = mn < (pad / 2);
        bool fmx  = (fs - mx) < ((1 + pad) / 2);
        if (!fmin && !fmx) { mn = mn - pad / 2; mx = mx + (1 + pad) / 2; }
        if (fmin) { mn = 0; mx = ps; }
        if (fmx)  { mn = fs - ps; mx = fs; }   // fmx overrides fmin (ref order)
    }
}

// ---------------------------------------------------------------------------
// Fused kernel, ONE BLOCK PER BOX (grid = B*N = 128, 256 threads).
// Phase 1: block computes its batch's NMS in smem (redundancy 32x per batch,
//          latency-parallel across SMs — cheap, unlike R9's 288x).
// Phase 2: pools all 9 cells of its box; 4 pixel-groups x 64 channel lanes,
//          9 register accumulators (statically unrolled), one smem reduce.
// ---------------------------------------------------------------------------
__global__ void __launch_bounds__(256)
roi_fused_kernel(const float* __restrict__ feat,
                 const float* __restrict__ roi,
                 float* __restrict__ out,
                 float* __restrict__ out_roic) {
    __shared__ float sx1[RR], sy1[RR], sx2[RR], sy2[RR], sar[RR];
    __shared__ uint32_t sup0[RR][4], sup1[RR][4];
    __shared__ int s_box[4];
    __shared__ float4 red[4][PS * PS * 64];   // 36 KB

    const int box = blockIdx.x;         // 0 .. B*N-1
    const int b   = box >> 5;           // batch
    const int n   = box & (NREG - 1);   // region index within batch
    const int t   = threadIdx.x;        // 0..255

    // ---- Phase 1a: load this batch's 128 boxes into smem -----------------
    if (t < RR) {
        const float* rp = roi + ((size_t)b * RR + t) * 4;
        float x = rp[0], y = rp[1], w = rp[2], h = rp[3];
        sx1[t] = x; sy1[t] = y; sx2[t] = x + w; sy2[t] = y + h; sar[t] = w * h;
    }
    __syncthreads();

    // ---- Phase 1b: suppression matrix. Row r split across 2 threads ------
    {
        const int r    = t & (RR - 1);
        const int half = t >> 7;        // 0 or 1
        float x = sx1[r], y = sy1[r], x2 = sx2[r], y2 = sy2[r], ar = sar[r];
        uint32_t row0 = 0, row1 = 0, row2 = 0, row3 = 0;
        for (int j = r + 1 + half; j < RR; j += 2) {
            float iw = fmaxf(fminf(x2, sx2[j]) - fmaxf(x, sx1[j]), 0.0f);
            float ih = fmaxf(fminf(y2, sy2[j]) - fmaxf(y, sy1[j]), 0.0f);
            float inter = iw * ih;
            float iou = __fdiv_rn(inter, ar + sar[j] - inter);  // IEEE rn
            if (iou > IOU_THR) {
                uint32_t bit = 1u << (j & 31);
                if      ((j >> 5) == 0) row0 |= bit;
                else if ((j >> 5) == 1) row1 |= bit;
                else if ((j >> 5) == 2) row2 |= bit;
                else                    row3 |= bit;
            }
        }
        uint32_t (*sp)[4] = half ? sup1 : sup0;
        sp[r][0] = row0; sp[r][1] = row1; sp[r][2] = row2; sp[r][3] = row3;
    }
    __syncthreads();

    // ---- Phase 1c: serial greedy walk + rank-select + clip (thread 0) ----
    if (t == 0) {
        uint32_t k0 = ~0u, k1 = ~0u, k2 = ~0u, k3 = ~0u;
        #pragma unroll 4
        for (int p = 0; p < RR - 1; ++p) {
            uint32_t s0 = sup0[p][0] | sup1[p][0];
            uint32_t s1 = sup0[p][1] | sup1[p][1];
            uint32_t s2 = sup0[p][2] | sup1[p][2];
            uint32_t s3 = sup0[p][3] | sup1[p][3];
            uint32_t kw = (p < 32) ? k0 : (p < 64) ? k1 : (p < 96) ? k2 : k3;
            uint32_t msk = 0u - ((kw >> (p & 31)) & 1u);
            k0 &= ~(s0 & msk); k1 &= ~(s1 & msk);
            k2 &= ~(s2 & msk); k3 &= ~(s3 & msk);
        }
        // n-th kept index via popcount rank walk; pad with R-1.
        uint32_t kwords[4] = {k0, k1, k2, k3};
        int p_sel = RR - 1;
        int rem = n;
        #pragma unroll
        for (int wrd = 0; wrd < 4; ++wrd) {
            uint32_t kw = kwords[wrd];
            int pc = __popc(kw);
            if (rem < pc) {
                uint32_t m = kw;
                for (int s = 0; s < rem; ++s) m &= m - 1;  // strip rem low bits
                p_sel = wrd * 32 + (__ffs(m) - 1);
                break;
            }
            rem -= pc;
        }
        // clip
        float bx = sx1[p_sel], by = sy1[p_sel], bx2 = sx2[p_sel], by2 = sy2[p_sel];
        int xmn = (int)fmaxf(0.0f, bx);
        int ymn = (int)fmaxf(0.0f, by);
        int xmx = (int)fminf((float)WW, bx2);
        int ymx = (int)fminf((float)HH, by2);
        fix_axis(xmn, xmx, PS, WW);
        fix_axis(ymn, ymx, PS, HH);
        s_box[0] = xmn; s_box[1] = ymn; s_box[2] = xmx - xmn; s_box[3] = ymx - ymn;

        int o = box * 4;                // this block owns exactly this box
        out_roic[o + 0] = (float)xmn;
        out_roic[o + 1] = (float)ymn;
        out_roic[o + 2] = (float)(xmx - xmn);
        out_roic[o + 3] = (float)(ymx - ymn);
    }
    __syncthreads();

    // ---- Phase 2: max-pool all 9 cells ------------------------------------
    const int x = s_box[0], y = s_box[1], w = s_box[2], h = s_box[3];
    const int d = h / PS;               // >= 1
    const int e = w / PS;

    const int g  = t >> 6;              // pixel group 0..3
    const int ch = t & 63;              // float4 channel lane

    const float4* __restrict__ f4 =
        (const float4*)feat + ((size_t)b * HH * WW) * (CC / 4) + ch;

    float4 acc[PS * PS];

    #pragma unroll
    for (int k = 0; k < PS * PS; ++k) {
        const int ci = k / 3, cj = k - (k / 3) * 3;
        const int r0 = y + ci * d;
        const int r1 = (ci < 2) ? (r0 + d) : (y + h);
        const int c0 = x + cj * e;
        const int c1 = (cj < 2) ? (c0 + e) : (x + w);
        const int ncol = c1 - c0;                 // >= 1
        const int npix = (r1 - r0) * ncol;        // >= 1
        const float inv = 1.0f / (float)ncol;

        float4 m = make_float4(-FLT_MAX, -FLT_MAX, -FLT_MAX, -FLT_MAX);
        // Independent iterations: (r,c) from linear index via guarded float
        // floor-div ((i+0.5)*inv; margin 0.5/ncol >= 0.0078 >> fp err ~1e-5).
        #pragma unroll 4
        for (int i = g; i < npix; i += 4) {
            int rr = (int)(((float)i + 0.5f) * inv);
            int cc = i - rr * ncol;
            float4 v = __ldg(f4 + (size_t)((r0 + rr) * WW + c0 + cc) * (CC / 4));
            m.x = fmaxf(m.x, v.x);
            m.y = fmaxf(m.y, v.y);
            m.z = fmaxf(m.z, v.z);
            m.w = fmaxf(m.w, v.w);
        }
        acc[k] = m;
    }

    // ---- Cross-group reduction (single smem pass for all 9 cells) --------
    #pragma unroll
    for (int k = 0; k < PS * PS; ++k)
        red[g][k * 64 + ch] = acc[k];
    __syncthreads();

    // 576 outputs, 256 threads -> up to 3 per thread.
    for (int idx = t; idx < PS * PS * 64; idx += 256) {
        float4 a0 = red[0][idx], a1 = red[1][idx];
        float4 a2 = red[2][idx], a3 = red[3][idx];
        float4 o;
        o.x = fmaxf(fmaxf(a0.x, a1.x), fmaxf(a2.x, a3.x));
        o.y = fmaxf(fmaxf(a0.y, a1.y), fmaxf(a2.y, a3.y));
        o.z = fmaxf(fmaxf(a0.z, a1.z), fmaxf(a2.z, a3.z));
        o.w = fmaxf(fmaxf(a0.w, a1.w), fmaxf(a2.w, a3.w));
        // pooled layout (B, N, 3, 3, C): f4 offset = (box*9 + cell)*64 + lane
        const int k  = idx >> 6;        // cell
        const int l  = idx & 63;        // channel lane
        ((float4*)out)[(size_t)(box * (PS * PS) + k) * (CC / 4) + l] = o;
    }
}

// ---------------------------------------------------------------------------
// Launch: out = [pooled (B*N*3*3*C floats) | roi_clipped (B*N*4 as floats)]
// ---------------------------------------------------------------------------
extern "C" void kernel_launch(void* const* d_in, const int* in_sizes, int n_in,
                              void* d_out, int out_size) {
    const float* features = (const float*)d_in[0];  // (B,H,W,C) f32
    const float* roi      = (const float*)d_in[1];  // (B,R,4)  f32
    float* out = (float*)d_out;

    const int pooled_elems = BB * NREG * PS * PS * CC;  // 294912

    roi_fused_kernel<<<BB * NREG, 256>>>(features, roi, out,
                                         out + pooled_elems);
}

// round 11
// speedup vs baseline: 2.2845x; 1.4071x over previous
#include <cuda_runtime.h>
#include <cuda_bf16.h>
#include <float.h>
#include <stdint.h>

// Problem constants
#define BB 4
#define RR 128
#define CC 256
#define HH 64
#define WW 64
#define NREG 32
#define PS 3            // pool size (3x3)
#define IOU_THR 0.4f
#define CLUSTER 8       // CTAs per cluster; 8 | 32 boxes/batch -> same batch

// ---------------------------------------------------------------------------
// Cluster / DSMEM helpers
// ---------------------------------------------------------------------------
__device__ __forceinline__ uint32_t s2u(const void* p) {
    return (uint32_t)__cvta_generic_to_shared(p);
}
__device__ __forceinline__ uint32_t mapa_addr(uint32_t laddr, uint32_t rank) {
    uint32_t r;
    asm("mapa.shared::cluster.u32 %0, %1, %2;" : "=r"(r) : "r"(laddr), "r"(rank));
    return r;
}
__device__ __forceinline__ void st_cluster(uint32_t raddr, uint32_t v) {
    asm volatile("st.shared::cluster.u32 [%0], %1;" :: "r"(raddr), "r"(v) : "memory");
}
__device__ __forceinline__ uint32_t ctarank() {
    uint32_t r; asm("mov.u32 %0, %%cluster_ctarank;" : "=r"(r)); return r;
}
__device__ __forceinline__ void cluster_sync_full() {
    asm volatile("fence.acq_rel.cluster;" ::: "memory");   // release my DSMEM stores
    asm volatile("barrier.cluster.arrive.aligned;" ::: "memory");
    asm volatile("barrier.cluster.wait.aligned;" ::: "memory");
    asm volatile("fence.acq_rel.cluster;" ::: "memory");   // acquire peers' stores
}

// ---------------------------------------------------------------------------
// fix_axis: exact replica of the reference clip logic.
// ---------------------------------------------------------------------------
__device__ __forceinline__ void fix_axis(int& mn, int& mx, int ps, int fs) {
    int pad = ps - (mx - mn);
    if (pad > 0) {
        bool fmin = mn < (pad / 2);
        bool fmx  = (fs - mx) < ((1 + pad) / 2);
        if (!fmin && !fmx) { mn = mn - pad / 2; mx = mx + (1 + pad) / 2; }
        if (fmin) { mn = 0; mx = ps; }
        if (fmx)  { mn = fs - ps; mx = fs; }   // fmx overrides fmin (ref order)
    }
}

// ---------------------------------------------------------------------------
// Fused kernel, ONE BLOCK PER BOX (grid = 128), clusters of 8 share the NMS:
//   - IoU matrix split across the 8 CTAs (1016 pairs each, div-free fast path)
//   - rows pushed into leader's smem (DSMEM), leader does the serial walk once
//   - leader pushes the 128-bit keep mask back to every CTA (no exit hazard)
//   - each CTA rank-selects its own box, clips, pools its 9 cells
// ---------------------------------------------------------------------------
__global__ void __launch_bounds__(256) __cluster_dims__(CLUSTER, 1, 1)
roi_fused_kernel(const float* __restrict__ feat,
                 const float* __restrict__ roi,
                 float* __restrict__ out,
                 float* __restrict__ out_roic) {
    __shared__ float sx1[RR], sy1[RR], sx2[RR], sy2[RR], sar[RR];
    __shared__ uint32_t sup[RR][4];       // leader only: full suppression matrix
    __shared__ uint32_t lsup[16][4];      // this CTA's 16 rows (partial OR)
    __shared__ uint32_t kshare[4];        // keep mask (pushed by leader)
    __shared__ int s_box[4];
    __shared__ float4 red4[4][PS * PS * 64];   // 36 KB

    const int box  = blockIdx.x;        // 0 .. B*N-1
    const int b    = box >> 5;          // batch
    const int n    = box & (NREG - 1);  // region index within batch
    const int t    = threadIdx.x;       // 0..255
    const uint32_t rank = ctarank();    // 0..7 within cluster

    // ---- Phase 1a: load this batch's 128 boxes; zero partial rows --------
    if (t < RR) {
        const float* rp = roi + ((size_t)b * RR + t) * 4;
        float x = rp[0], y = rp[1], w = rp[2], h = rp[3];
        sx1[t] = x; sy1[t] = y; sx2[t] = x + w; sy2[t] = y + h; sar[t] = w * h;
    }
    if (t < 64) lsup[t >> 2][t & 3] = 0u;
    __syncthreads();

    // ---- Phase 1b: this CTA owns rows r = lr*8 + rank (lr = 0..15).
    //      16 threads per row, each handles j = r+1+sub, step 16.
    {
        const int lr  = t >> 4;                 // 0..15
        const int sub = t & 15;
        const int r   = lr * 8 + (int)rank;     // 0..127
        float x = sx1[r], y = sy1[r], x2 = sx2[r], y2 = sy2[r], ar = sar[r];
        uint32_t row0 = 0, row1 = 0, row2 = 0, row3 = 0;
        for (int j = r + 1 + sub; j < RR; j += 16) {
            float iw = fmaxf(fminf(x2, sx2[j]) - fmaxf(x, sx1[j]), 0.0f);
            float ih = fmaxf(fminf(y2, sy2[j]) - fmaxf(y, sy1[j]), 0.0f);
            float inter = iw * ih;
            float uni   = ar + sar[j] - inter;          // > 0 always (areas >= 16)
            // Division-free compare with exact fallback:
            // iou > thr  <=>  inter - thr*uni > 0. If |diff| > 1e-4*uni the
            // sign decides (margin >> any rounding of either formulation);
            // otherwise take the IEEE-rn division exactly like the reference.
            float diff = fmaf(-IOU_THR, uni, inter);
            bool over;
            if (fabsf(diff) > 1e-4f * uni) over = (diff > 0.0f);
            else over = (__fdiv_rn(inter, uni) > IOU_THR);
            if (over) {
                uint32_t bit = 1u << (j & 31);
                if      ((j >> 5) == 0) row0 |= bit;
                else if ((j >> 5) == 1) row1 |= bit;
                else if ((j >> 5) == 2) row2 |= bit;
                else                    row3 |= bit;
            }
        }
        if (row0) atomicOr_block(&lsup[lr][0], row0);
        if (row1) atomicOr_block(&lsup[lr][1], row1);
        if (row2) atomicOr_block(&lsup[lr][2], row2);
        if (row3) atomicOr_block(&lsup[lr][3], row3);
    }
    __syncthreads();

    // ---- Push this CTA's 16 rows into the LEADER's sup matrix ------------
    if (t < 64) {
        const int lr = t >> 2, w = t & 3;
        const int r  = lr * 8 + (int)rank;
        uint32_t dst = mapa_addr(s2u(&sup[r][w]), 0);
        st_cluster(dst, lsup[lr][w]);
    }
    cluster_sync_full();                 // sup complete in leader's smem

    // ---- Leader: serial greedy walk once; push keep mask to all CTAs -----
    if (rank == 0 && t == 0) {
        uint32_t k0 = ~0u, k1 = ~0u, k2 = ~0u, k3 = ~0u;
        #pragma unroll 4
        for (int p = 0; p < RR - 1; ++p) {
            uint32_t s0 = sup[p][0], s1 = sup[p][1];
            uint32_t s2 = sup[p][2], s3 = sup[p][3];
            uint32_t kw = (p < 32) ? k0 : (p < 64) ? k1 : (p < 96) ? k2 : k3;
            uint32_t msk = 0u - ((kw >> (p & 31)) & 1u);
            k0 &= ~(s0 & msk); k1 &= ~(s1 & msk);
            k2 &= ~(s2 & msk); k3 &= ~(s3 & msk);
        }
        uint32_t kwords[4] = {k0, k1, k2, k3};
        #pragma unroll
        for (int rk = 0; rk < CLUSTER; ++rk) {
            #pragma unroll
            for (int w = 0; w < 4; ++w)
                st_cluster(mapa_addr(s2u(&kshare[w]), rk), kwords[w]);
        }
    }
    cluster_sync_full();                 // kshare valid in every CTA's own smem
    // (no remote accesses after this point -> safe CTA exit)

    // ---- Rank-select this block's box, clip (thread 0) -------------------
    if (t == 0) {
        uint32_t kwords[4] = {kshare[0], kshare[1], kshare[2], kshare[3]};
        int p_sel = RR - 1;
        int rem = n;
        #pragma unroll
        for (int wrd = 0; wrd < 4; ++wrd) {
            uint32_t kw = kwords[wrd];
            int pc = __popc(kw);
            if (rem < pc) {
                uint32_t m = kw;
                for (int s = 0; s < rem; ++s) m &= m - 1;  // strip rem low bits
                p_sel = wrd * 32 + (__ffs(m) - 1);
                break;
            }
            rem -= pc;
        }
        float bx = sx1[p_sel], by = sy1[p_sel], bx2 = sx2[p_sel], by2 = sy2[p_sel];
        int xmn = (int)fmaxf(0.0f, bx);
        int ymn = (int)fmaxf(0.0f, by);
        int xmx = (int)fminf((float)WW, bx2);
        int ymx = (int)fminf((float)HH, by2);
        fix_axis(xmn, xmx, PS, WW);
        fix_axis(ymn, ymx, PS, HH);
        s_box[0] = xmn; s_box[1] = ymn; s_box[2] = xmx - xmn; s_box[3] = ymx - ymn;

        int o = box * 4;
        out_roic[o + 0] = (float)xmn;
        out_roic[o + 1] = (float)ymn;
        out_roic[o + 2] = (float)(xmx - xmn);
        out_roic[o + 3] = (float)(ymx - ymn);
    }
    __syncthreads();

    // ---- Phase 2: max-pool all 9 cells ------------------------------------
    const int x = s_box[0], y = s_box[1], w = s_box[2], h = s_box[3];
    const int d = h / PS;               // >= 1
    const int e = w / PS;

    const int g  = t >> 6;              // pixel group 0..3
    const int ch = t & 63;              // float4 channel lane

    const float4* __restrict__ f4 =
        (const float4*)feat + ((size_t)b * HH * WW) * (CC / 4) + ch;

    float4 acc[PS * PS];

    #pragma unroll
    for (int k = 0; k < PS * PS; ++k) {
        const int ci = k / 3, cj = k - (k / 3) * 3;
        const int r0 = y + ci * d;
        const int r1 = (ci < 2) ? (r0 + d) : (y + h);
        const int c0 = x + cj * e;
        const int c1 = (cj < 2) ? (c0 + e) : (x + w);
        const int ncol = c1 - c0;                 // >= 1
        const int npix = (r1 - r0) * ncol;        // >= 1
        const float inv = 1.0f / (float)ncol;

        float4 m = make_float4(-FLT_MAX, -FLT_MAX, -FLT_MAX, -FLT_MAX);
        // Independent iterations: (r,c) from linear index via guarded float
        // floor-div ((i+0.5)*inv; margin 0.5/ncol >= 0.0078 >> fp err ~1e-5).
        #pragma unroll 4
        for (int i = g; i < npix; i += 4) {
            int rr = (int)(((float)i + 0.5f) * inv);
            int cc = i - rr * ncol;
            float4 v = __ldg(f4 + (size_t)((r0 + rr) * WW + c0 + cc) * (CC / 4));
            m.x = fmaxf(m.x, v.x);
            m.y = fmaxf(m.y, v.y);
            m.z = fmaxf(m.z, v.z);
            m.w = fmaxf(m.w, v.w);
        }
        acc[k] = m;
    }

    // ---- Cross-group reduction (single smem pass for all 9 cells) --------
    #pragma unroll
    for (int k = 0; k < PS * PS; ++k)
        red4[g][k * 64 + ch] = acc[k];
    __syncthreads();

    for (int idx = t; idx < PS * PS * 64; idx += 256) {
        float4 a0 = red4[0][idx], a1 = red4[1][idx];
        float4 a2 = red4[2][idx], a3 = red4[3][idx];
        float4 o;
        o.x = fmaxf(fmaxf(a0.x, a1.x), fmaxf(a2.x, a3.x));
        o.y = fmaxf(fmaxf(a0.y, a1.y), fmaxf(a2.y, a3.y));
        o.z = fmaxf(fmaxf(a0.z, a1.z), fmaxf(a2.z, a3.z));
        o.w = fmaxf(fmaxf(a0.w, a1.w), fmaxf(a2.w, a3.w));
        const int k = idx >> 6;         // cell
        const int l = idx & 63;         // channel lane
        ((float4*)out)[(size_t)(box * (PS * PS) + k) * (CC / 4) + l] = o;
    }
}

// ---------------------------------------------------------------------------
// Launch: out = [pooled (B*N*3*3*C floats) | roi_clipped (B*N*4 as floats)]
// ---------------------------------------------------------------------------
extern "C" void kernel_launch(void* const* d_in, const int* in_sizes, int n_in,
                              void* d_out, int out_size) {
    const float* features = (const float*)d_in[0];  // (B,H,W,C) f32
    const float* roi      = (const float*)d_in[1];  // (B,R,4)  f32
    float* out = (float*)d_out;

    const int pooled_elems = BB * NREG * PS * PS * CC;  // 294912

    roi_fused_kernel<<<BB * NREG, 256>>>(features, roi, out,
                                         out + pooled_elems);
}

// round 12
// speedup vs baseline: 2.8820x; 1.2616x over previous
#include <cuda_runtime.h>
#include <cuda_bf16.h>
#include <float.h>
#include <stdint.h>

// Problem constants
#define BB 4
#define RR 128
#define CC 256
#define HH 64
#define WW 64
#define NREG 32
#define PS 3            // pool size (3x3)
#define IOU_THR 0.4f
#define CLUSTER 8       // CTAs per cluster; 288 bids/batch, 288%8==0 -> batch-uniform

// ---------------------------------------------------------------------------
// Cluster / DSMEM helpers
// ---------------------------------------------------------------------------
__device__ __forceinline__ uint32_t s2u(const void* p) {
    return (uint32_t)__cvta_generic_to_shared(p);
}
__device__ __forceinline__ uint32_t mapa_addr(uint32_t laddr, uint32_t rank) {
    uint32_t r;
    asm("mapa.shared::cluster.u32 %0, %1, %2;" : "=r"(r) : "r"(laddr), "r"(rank));
    return r;
}
__device__ __forceinline__ void st_cluster(uint32_t raddr, uint32_t v) {
    asm volatile("st.shared::cluster.u32 [%0], %1;" :: "r"(raddr), "r"(v) : "memory");
}
__device__ __forceinline__ uint32_t ctarank() {
    uint32_t r; asm("mov.u32 %0, %%cluster_ctarank;" : "=r"(r)); return r;
}
__device__ __forceinline__ void cluster_sync_full() {
    asm volatile("fence.acq_rel.cluster;" ::: "memory");   // release my DSMEM stores
    asm volatile("barrier.cluster.arrive.aligned;" ::: "memory");
    asm volatile("barrier.cluster.wait.aligned;" ::: "memory");
    asm volatile("fence.acq_rel.cluster;" ::: "memory");   // acquire peers' stores
}

// ---------------------------------------------------------------------------
// fix_axis: exact replica of the reference clip logic.
// ---------------------------------------------------------------------------
__device__ __forceinline__ void fix_axis(int& mn, int& mx, int ps, int fs) {
    int pad = ps - (mx - mn);
    if (pad > 0) {
        bool fmin = mn < (pad / 2);
        bool fmx  = (fs - mx) < ((1 + pad) / 2);
        if (!fmin && !fmx) { mn = mn - pad / 2; mx = mx + (1 + pad) / 2; }
        if (fmin) { mn = 0; mx = ps; }
        if (fmx)  { mn = fs - ps; mx = fs; }   // fmx overrides fmin (ref order)
    }
}

// ---------------------------------------------------------------------------
// Fused kernel, ONE CTA PER (box, cell): grid = B*N*9 = 1152, 128 threads.
// Clusters of 8 CTAs (batch-uniform) share the NMS:
//   - IoU matrix split across the 8 CTAs (rows r == rank mod 8)
//   - rows pushed into leader's smem (DSMEM), leader walks once
//   - leader pushes the 128-bit keep mask back to every CTA (no exit hazard)
//   - each CTA rank-selects its own box, clips, pools its single 3x3 cell
// 128 threads = 2 pixel-groups x 64 float4-channel lanes.
// ---------------------------------------------------------------------------
__global__ void __launch_bounds__(128) __cluster_dims__(CLUSTER, 1, 1)
roi_fused_kernel(const float* __restrict__ feat,
                 const float* __restrict__ roi,
                 float* __restrict__ out,
                 float* __restrict__ out_roic) {
    __shared__ float sx1[RR], sy1[RR], sx2[RR], sy2[RR], sar[RR];
    __shared__ uint32_t sup[RR][4];       // leader only: full suppression matrix
    __shared__ uint32_t lsup[16][4];      // this CTA's 16 rows (partial OR)
    __shared__ uint32_t kshare[4];        // keep mask (pushed by leader)
    __shared__ int s_box[4];
    __shared__ float4 red4[2][64];

    const int bid  = blockIdx.x;        // 0 .. B*N*9-1
    const int box  = bid / 9;           // 0 .. B*N-1
    const int cell = bid - box * 9;
    const int ci   = cell / 3;
    const int cj   = cell - ci * 3;
    const int b    = box >> 5;          // batch
    const int n    = box & (NREG - 1);  // region index within batch
    const int t    = threadIdx.x;       // 0..127
    const uint32_t rank = ctarank();    // 0..7 within cluster

    // ---- Phase 1a: load this batch's 128 boxes; zero partial rows --------
    {
        const float* rp = roi + ((size_t)b * RR + t) * 4;
        float x = rp[0], y = rp[1], w = rp[2], h = rp[3];
        sx1[t] = x; sy1[t] = y; sx2[t] = x + w; sy2[t] = y + h; sar[t] = w * h;
    }
    if (t < 64) lsup[t >> 2][t & 3] = 0u;
    __syncthreads();

    // ---- Phase 1b: this CTA owns rows r = lr*8 + rank (lr = 0..15).
    //      8 threads per row, each handles j = r+1+sub, step 8.
    {
        const int lr  = t >> 3;                 // 0..15
        const int sub = t & 7;
        const int r   = lr * 8 + (int)rank;     // 0..127
        float x = sx1[r], y = sy1[r], x2 = sx2[r], y2 = sy2[r], ar = sar[r];
        uint32_t row0 = 0, row1 = 0, row2 = 0, row3 = 0;
        for (int j = r + 1 + sub; j < RR; j += 8) {
            float iw = fmaxf(fminf(x2, sx2[j]) - fmaxf(x, sx1[j]), 0.0f);
            float ih = fmaxf(fminf(y2, sy2[j]) - fmaxf(y, sy1[j]), 0.0f);
            float inter = iw * ih;
            float uni   = ar + sar[j] - inter;          // > 0 always
            // Division-free compare with exact fallback: iou > thr <=>
            // inter - thr*uni > 0; if |diff| > 1e-4*uni the sign decides
            // (margin >> rounding), else do the IEEE-rn division like the ref.
            float diff = fmaf(-IOU_THR, uni, inter);
            bool over;
            if (fabsf(diff) > 1e-4f * uni) over = (diff > 0.0f);
            else over = (__fdiv_rn(inter, uni) > IOU_THR);
            if (over) {
                uint32_t bit = 1u << (j & 31);
                if      ((j >> 5) == 0) row0 |= bit;
                else if ((j >> 5) == 1) row1 |= bit;
                else if ((j >> 5) == 2) row2 |= bit;
                else                    row3 |= bit;
            }
        }
        if (row0) atomicOr_block(&lsup[lr][0], row0);
        if (row1) atomicOr_block(&lsup[lr][1], row1);
        if (row2) atomicOr_block(&lsup[lr][2], row2);
        if (row3) atomicOr_block(&lsup[lr][3], row3);
    }
    __syncthreads();

    // ---- Push this CTA's 16 rows into the LEADER's sup matrix ------------
    if (t < 64) {
        const int lr = t >> 2, w = t & 3;
        const int r  = lr * 8 + (int)rank;
        uint32_t dst = mapa_addr(s2u(&sup[r][w]), 0);
        st_cluster(dst, lsup[lr][w]);
    }
    cluster_sync_full();                 // sup complete in leader's smem

    // ---- Leader: serial greedy walk once; push keep mask to all CTAs -----
    if (rank == 0 && t == 0) {
        uint32_t k0 = ~0u, k1 = ~0u, k2 = ~0u, k3 = ~0u;
        #pragma unroll 4
        for (int p = 0; p < RR - 1; ++p) {
            uint32_t s0 = sup[p][0], s1 = sup[p][1];
            uint32_t s2 = sup[p][2], s3 = sup[p][3];
            uint32_t kw = (p < 32) ? k0 : (p < 64) ? k1 : (p < 96) ? k2 : k3;
            uint32_t msk = 0u - ((kw >> (p & 31)) & 1u);
            k0 &= ~(s0 & msk); k1 &= ~(s1 & msk);
            k2 &= ~(s2 & msk); k3 &= ~(s3 & msk);
        }
        uint32_t kwords[4] = {k0, k1, k2, k3};
        #pragma unroll
        for (int rk = 0; rk < CLUSTER; ++rk) {
            #pragma unroll
            for (int w = 0; w < 4; ++w)
                st_cluster(mapa_addr(s2u(&kshare[w]), rk), kwords[w]);
        }
    }
    cluster_sync_full();                 // kshare valid in every CTA's own smem
    // (no remote accesses after this point -> safe CTA exit)

    // ---- Rank-select this block's box, clip (thread 0) -------------------
    if (t == 0) {
        uint32_t kwords[4] = {kshare[0], kshare[1], kshare[2], kshare[3]};
        int p_sel = RR - 1;
        int rem = n;
        #pragma unroll
        for (int wrd = 0; wrd < 4; ++wrd) {
            uint32_t kw = kwords[wrd];
            int pc = __popc(kw);
            if (rem < pc) {
                uint32_t m = kw;
                for (int s = 0; s < rem; ++s) m &= m - 1;  // strip rem low bits
                p_sel = wrd * 32 + (__ffs(m) - 1);
                break;
            }
            rem -= pc;
        }
        float bx = sx1[p_sel], by = sy1[p_sel], bx2 = sx2[p_sel], by2 = sy2[p_sel];
        int xmn = (int)fmaxf(0.0f, bx);
        int ymn = (int)fmaxf(0.0f, by);
        int xmx = (int)fminf((float)WW, bx2);
        int ymx = (int)fminf((float)HH, by2);
        fix_axis(xmn, xmx, PS, WW);
        fix_axis(ymn, ymx, PS, HH);
        s_box[0] = xmn; s_box[1] = ymn; s_box[2] = xmx - xmn; s_box[3] = ymx - ymn;

        if (cell == 0) {                 // one CTA per box writes the roic tail
            int o = box * 4;
            out_roic[o + 0] = (float)xmn;
            out_roic[o + 1] = (float)ymn;
            out_roic[o + 2] = (float)(xmx - xmn);
            out_roic[o + 3] = (float)(ymx - ymn);
        }
    }
    __syncthreads();

    // ---- Phase 2: max-pool this cell --------------------------------------
    const int x = s_box[0], y = s_box[1], w = s_box[2], h = s_box[3];
    const int d = h / PS;               // >= 1
    const int e = w / PS;
    const int r0 = y + ci * d;
    const int r1 = (ci < 2) ? (r0 + d) : (y + h);
    const int c0 = x + cj * e;
    const int c1 = (cj < 2) ? (c0 + e) : (x + w);

    const int g  = t >> 6;              // pixel group 0..1
    const int ch = t & 63;              // float4 channel lane

    const int ncol = c1 - c0;           // >= 1
    const int npix = (r1 - r0) * ncol;  // >= 1
    const float inv = 1.0f / (float)ncol;

    const float4* __restrict__ f4 =
        (const float4*)feat + ((size_t)b * HH * WW) * (CC / 4) + ch;

    float4 m = make_float4(-FLT_MAX, -FLT_MAX, -FLT_MAX, -FLT_MAX);

    // Independent iterations: (r,c) from linear index via guarded float
    // floor-div ((i+0.5)*inv; margin 0.5/ncol >= 0.0078 >> fp err ~1e-5).
    #pragma unroll 4
    for (int i = g; i < npix; i += 2) {
        int rr = (int)(((float)i + 0.5f) * inv);
        int cc = i - rr * ncol;
        float4 v = __ldg(f4 + (size_t)((r0 + rr) * WW + c0 + cc) * (CC / 4));
        m.x = fmaxf(m.x, v.x);
        m.y = fmaxf(m.y, v.y);
        m.z = fmaxf(m.z, v.z);
        m.w = fmaxf(m.w, v.w);
    }

    red4[g][ch] = m;
    __syncthreads();

    if (t < 64) {
        float4 a0 = red4[0][t], a1 = red4[1][t];
        float4 o;
        o.x = fmaxf(a0.x, a1.x);
        o.y = fmaxf(a0.y, a1.y);
        o.z = fmaxf(a0.z, a1.z);
        o.w = fmaxf(a0.w, a1.w);
        // pooled layout (B, N, 3, 3, C): f4 offset = bid*64 + lane
        ((float4*)out)[(size_t)bid * (CC / 4) + t] = o;
    }
}

// ---------------------------------------------------------------------------
// Launch: out = [pooled (B*N*3*3*C floats) | roi_clipped (B*N*4 as floats)]
// ---------------------------------------------------------------------------
extern "C" void kernel_launch(void* const* d_in, const int* in_sizes, int n_in,
                              void* d_out, int out_size) {
    const float* features = (const float*)d_in[0];  // (B,H,W,C) f32
    const float* roi      = (const float*)d_in[1];  // (B,R,4)  f32
    float* out = (float*)d_out;

    const int pooled_elems = BB * NREG * PS * PS * CC;  // 294912

    roi_fused_kernel<<<BB * NREG * PS * PS, 128>>>(features, roi, out,
                                                   out + pooled_elems);
}

// round 15
// speedup vs baseline: 3.0524x; 1.0591x over previous
#include <cuda_runtime.h>
#include <cuda_bf16.h>
#include <float.h>
#include <stdint.h>

// Problem constants
#define BB 4
#define RR 128
#define CC 256
#define HH 64
#define WW 64
#define NREG 32
#define PS 3            // pool size (3x3)
#define IOU_THR 0.4f
#define CLUSTER 8       // CTAs per cluster; 288 bids/batch, 288%8==0 -> batch-uniform

// ---------------------------------------------------------------------------
// Cluster / DSMEM helpers
// ---------------------------------------------------------------------------
__device__ __forceinline__ uint32_t s2u(const void* p) {
    return (uint32_t)__cvta_generic_to_shared(p);
}
__device__ __forceinline__ uint32_t mapa_addr(uint32_t laddr, uint32_t rank) {
    uint32_t r;
    asm("mapa.shared::cluster.u32 %0, %1, %2;" : "=r"(r) : "r"(laddr), "r"(rank));
    return r;
}
__device__ __forceinline__ uint32_t ld_cluster(uint32_t raddr) {
    uint32_t v;
    asm volatile("ld.shared::cluster.u32 %0, [%1];" : "=r"(v) : "r"(raddr) : "memory");
    return v;
}
__device__ __forceinline__ uint32_t ctarank() {
    uint32_t r; asm("mov.u32 %0, %%cluster_ctarank;" : "=r"(r)); return r;
}
// arrive: release (default), wait: acquire (default) — no explicit fences,
// avoids the extra CCTL.IVALL L1 flushes of fence.acq_rel.cluster.
__device__ __forceinline__ void cluster_arrive_rel() {
    asm volatile("barrier.cluster.arrive.aligned;" ::: "memory");
}
__device__ __forceinline__ void cluster_arrive_relaxed() {
    asm volatile("barrier.cluster.arrive.relaxed.aligned;" ::: "memory");
}
__device__ __forceinline__ void cluster_wait_acq() {
    asm volatile("barrier.cluster.wait.aligned;" ::: "memory");
}

// ---------------------------------------------------------------------------
// fix_axis: exact replica of the reference clip logic.
// ---------------------------------------------------------------------------
__device__ __forceinline__ void fix_axis(int& mn, int& mx, int ps, int fs) {
    int pad = ps - (mx - mn);
    if (pad > 0) {
        bool fmin = mn < (pad / 2);
        bool fmx  = (fs - mx) < ((1 + pad) / 2);
        if (!fmin && !fmx) { mn = mn - pad / 2; mx = mx + (1 + pad) / 2; }
        if (fmin) { mn = 0; mx = ps; }
        if (fmx)  { mn = fs - ps; mx = fs; }   // fmx overrides fmin (ref order)
    }
}

// ---------------------------------------------------------------------------
// Fused kernel, ONE CTA PER (box, cell): grid = B*N*9 = 1152, 128 threads.
// Clusters of 8 CTAs (batch-uniform) share the IoU build:
//   - each CTA computes rows r (r mod 8 == rank), octet shfl-OR reduce
//   - ONE cluster sync; every CTA pulls all 128 rows (peers via DSMEM reads)
//   - every CTA walks the greedy NMS itself (1 thread, latency-only,
//     redundancy is free — no leader, no second sync on the critical path)
//   - arrive.relaxed right after the pulls + wait at kernel end guards the
//     lifetime of peer smem (off the critical path)
// 128 threads = 2 pixel-groups x 64 float4-channel lanes for the pool.
// ---------------------------------------------------------------------------
__global__ void __launch_bounds__(128) __cluster_dims__(CLUSTER, 1, 1)
roi_fused_kernel(const float* __restrict__ feat,
                 const float* __restrict__ roi,
                 float* __restrict__ out,
                 float* __restrict__ out_roic) {
    __shared__ float sx1[RR], sy1[RR], sx2[RR], sy2[RR], sar[RR];
    __shared__ uint32_t sup[RR][4];       // full suppression matrix (assembled)
    __shared__ uint32_t lsup[16][4];      // this CTA's 16 rows
    __shared__ int s_box[4];
    __shared__ float4 red4[2][64];

    const int bid  = blockIdx.x;        // 0 .. B*N*9-1
    const int box  = bid / 9;           // 0 .. B*N-1
    const int cell = bid - box * 9;
    const int ci   = cell / 3;
    const int cj   = cell - ci * 3;
    const int b    = box >> 5;          // batch
    const int n    = box & (NREG - 1);  // region index within batch
    const int t    = threadIdx.x;       // 0..127
    const uint32_t rank = ctarank();    // 0..7 within cluster

    // ---- Phase 1a: load this batch's 128 boxes (one float4 per thread) ---
    {
        float4 bx = __ldg((const float4*)(roi + ((size_t)b * RR + t) * 4));
        sx1[t] = bx.x; sy1[t] = bx.y;
        sx2[t] = bx.x + bx.z; sy2[t] = bx.y + bx.w;
        sar[t] = bx.z * bx.w;
    }
    __syncthreads();

    // ---- Phase 1b: rows r = lr*8 + rank (lr = 0..15), 8 threads per row --
    {
        const int lr  = t >> 3;                 // 0..15
        const int sub = t & 7;
        const int r   = lr * 8 + (int)rank;     // 0..127
        float x = sx1[r], y = sy1[r], x2 = sx2[r], y2 = sy2[r], ar = sar[r];
        uint32_t row0 = 0, row1 = 0, row2 = 0, row3 = 0;
        for (int j = r + 1 + sub; j < RR; j += 8) {
            float iw = fmaxf(fminf(x2, sx2[j]) - fmaxf(x, sx1[j]), 0.0f);
            float ih = fmaxf(fminf(y2, sy2[j]) - fmaxf(y, sy1[j]), 0.0f);
            float inter = iw * ih;
            float uni   = ar + sar[j] - inter;          // > 0 always
            // Division-free compare with exact fallback: iou > thr <=>
            // inter - thr*uni > 0; if |diff| > 1e-4*uni the sign decides
            // (margin >> rounding), else do the IEEE-rn division like the ref.
            float diff = fmaf(-IOU_THR, uni, inter);
            bool over;
            if (fabsf(diff) > 1e-4f * uni) over = (diff > 0.0f);
            else over = (__fdiv_rn(inter, uni) > IOU_THR);
            if (over) {
                uint32_t bit = 1u << (j & 31);
                if      ((j >> 5) == 0) row0 |= bit;
                else if ((j >> 5) == 1) row1 |= bit;
                else if ((j >> 5) == 2) row2 |= bit;
                else                    row3 |= bit;
            }
        }
        // OR-reduce across the 8-lane octet (xor lanes 1,2,4 stay in-octet)
        #pragma unroll
        for (int s = 1; s < 8; s <<= 1) {
            row0 |= __shfl_xor_sync(0xffffffffu, row0, s);
            row1 |= __shfl_xor_sync(0xffffffffu, row1, s);
            row2 |= __shfl_xor_sync(0xffffffffu, row2, s);
            row3 |= __shfl_xor_sync(0xffffffffu, row3, s);
        }
        if (sub == 0) {
            lsup[lr][0] = row0; lsup[lr][1] = row1;
            lsup[lr][2] = row2; lsup[lr][3] = row3;
        }
    }
    __syncthreads();          // lsup visible CTA-wide before the cluster sync

    // ---- Sync 1: publish lsup cluster-wide --------------------------------
    cluster_arrive_rel();
    cluster_wait_acq();

    // ---- Pull all 128 rows into local sup (peers via DSMEM) ---------------
    // 512 words, 128 threads -> 4 independent reads each (MLP 4).
    #pragma unroll
    for (int idx = t; idx < RR * 4; idx += 128) {
        const int rowg = idx >> 2, w = idx & 3;
        const int rk   = rowg & 7;            // owner rank
        const int lr   = rowg >> 3;
        uint32_t v;
        if ((uint32_t)rk == rank) v = lsup[lr][w];
        else                      v = ld_cluster(mapa_addr(s2u(&lsup[lr][w]), rk));
        sup[rowg][w] = v;
    }
    // Done touching peer smem: lifetime arrive now, wait at kernel end.
    cluster_arrive_relaxed();
    __syncthreads();

    // ---- Greedy walk + rank-select + clip (thread 0, per CTA) -------------
    if (t == 0) {
        uint32_t k0 = ~0u, k1 = ~0u, k2 = ~0u, k3 = ~0u;
        #pragma unroll 4
        for (int p = 0; p < RR - 1; ++p) {
            uint32_t s0 = sup[p][0], s1 = sup[p][1];
            uint32_t s2 = sup[p][2], s3 = sup[p][3];
            uint32_t kw = (p < 32) ? k0 : (p < 64) ? k1 : (p < 96) ? k2 : k3;
            uint32_t msk = 0u - ((kw >> (p & 31)) & 1u);
            k0 &= ~(s0 & msk); k1 &= ~(s1 & msk);
            k2 &= ~(s2 & msk); k3 &= ~(s3 & msk);
        }
        // n-th kept index via popcount rank walk; pad with R-1.
        uint32_t kwords[4] = {k0, k1, k2, k3};
        int p_sel = RR - 1;
        int rem = n;
        #pragma unroll
        for (int wrd = 0; wrd < 4; ++wrd) {
            uint32_t kw = kwords[wrd];
            int pc = __popc(kw);
            if (rem < pc) {
                uint32_t m = kw;
                for (int s = 0; s < rem; ++s) m &= m - 1;  // strip rem low bits
                p_sel = wrd * 32 + (__ffs(m) - 1);
                break;
            }
            rem -= pc;
        }
        float bx = sx1[p_sel], by = sy1[p_sel], bx2 = sx2[p_sel], by2 = sy2[p_sel];
        int xmn = (int)fmaxf(0.0f, bx);
        int ymn = (int)fmaxf(0.0f, by);
        int xmx = (int)fminf((float)WW, bx2);
        int ymx = (int)fminf((float)HH, by2);
        fix_axis(xmn, xmx, PS, WW);
        fix_axis(ymn, ymx, PS, HH);
        s_box[0] = xmn; s_box[1] = ymn; s_box[2] = xmx - xmn; s_box[3] = ymx - ymn;

        if (cell == 0) {                 // one CTA per box writes the roic tail
            int o = box * 4;
            out_roic[o + 0] = (float)xmn;
            out_roic[o + 1] = (float)ymn;
            out_roic[o + 2] = (float)(xmx - xmn);
            out_roic[o + 3] = (float)(ymx - ymn);
        }
    }
    __syncthreads();

    // ---- Phase 2: max-pool this cell --------------------------------------
    const int x = s_box[0], y = s_box[1], w = s_box[2], h = s_box[3];
    const int d = h / PS;               // >= 1
    const int e = w / PS;
    const int r0 = y + ci * d;
    const int r1 = (ci < 2) ? (r0 + d) : (y + h);
    const int c0 = x + cj * e;
    const int c1 = (cj < 2) ? (c0 + e) : (x + w);

    const int g  = t >> 6;              // pixel group 0..1
    const int ch = t & 63;              // float4 channel lane

    const int ncol = c1 - c0;           // >= 1
    const int npix = (r1 - r0) * ncol;  // >= 1
    const float inv = 1.0f / (float)ncol;

    const float4* __restrict__ f4 =
        (const float4*)feat + ((size_t)b * HH * WW) * (CC / 4) + ch;

    float4 m = make_float4(-FLT_MAX, -FLT_MAX, -FLT_MAX, -FLT_MAX);

    // Independent iterations: (r,c) from linear index via guarded float
    // floor-div ((i+0.5)*inv; margin 0.5/ncol >= 0.0078 >> fp err ~1e-5).
    #pragma unroll 4
    for (int i = g; i < npix; i += 2) {
        int rr = (int)(((float)i + 0.5f) * inv);
        int cc = i - rr * ncol;
        float4 v = __ldg(f4 + (size_t)((r0 + rr) * WW + c0 + cc) * (CC / 4));
        m.x = fmaxf(m.x, v.x);
        m.y = fmaxf(m.y, v.y);
        m.z = fmaxf(m.z, v.z);
        m.w = fmaxf(m.w, v.w);
    }

    red4[g][ch] = m;
    __syncthreads();

    if (t < 64) {
        float4 a0 = red4[0][t], a1 = red4[1][t];
        float4 o;
        o.x = fmaxf(a0.x, a1.x);
        o.y = fmaxf(a0.y, a1.y);
        o.z = fmaxf(a0.z, a1.z);
        o.w = fmaxf(a0.w, a1.w);
        // pooled layout (B, N, 3, 3, C): f4 offset = bid*64 + lane
        ((float4*)out)[(size_t)bid * (CC / 4) + t] = o;
    }

    // ---- Lifetime guard: no CTA exits while peers might read its smem ----
    cluster_wait_acq();
}

// ---------------------------------------------------------------------------
// Launch: out = [pooled (B*N*3*3*C floats) | roi_clipped (B*N*4 as floats)]
// ---------------------------------------------------------------------------
extern "C" void kernel_launch(void* const* d_in, const int* in_sizes, int n_in,
                              void* d_out, int out_size) {
    const float* features = (const float*)d_in[0];  // (B,H,W,C) f32
    const float* roi      = (const float*)d_in[1];  // (B,R,4)  f32
    float* out = (float*)d_out;

    const int pooled_elems = BB * NREG * PS * PS * CC;  // 294912

    roi_fused_kernel<<<BB * NREG * PS * PS, 128>>>(features, roi, out,
                                                   out + pooled_elems);
}